// round 7
// baseline (speedup 1.0000x reference)
#include <cuda_runtime.h>
#include <cstdint>
#include <cstddef>

#define BATCH 8
#define TLEN 2048
#define DIN 1024
#define HD 64
#define BT (BATCH*TLEN)

// Scratch for projections (no cudaMalloc allowed). Stored pre-rounded to tf32.
__device__ float g_q[BT*HD];
__device__ float g_k[BT*HD];
__device__ float g_v[BT*HD];

// ---------------------------------------------------------------------------
// tf32 + cp.async helpers
// ---------------------------------------------------------------------------
__device__ __forceinline__ uint32_t f2tf32(float f) {
    uint32_t u;
    asm("cvt.rna.tf32.f32 %0, %1;" : "=r"(u) : "f"(f));
    return u;
}
__device__ __forceinline__ float f2tf32f(float f) {
    return __uint_as_float(f2tf32(f));
}

__device__ __forceinline__ void mma_tf32(
    float& c0, float& c1, float& c2, float& c3,
    uint32_t a0, uint32_t a1, uint32_t a2, uint32_t a3,
    uint32_t b0, uint32_t b1)
{
    asm volatile(
        "mma.sync.aligned.m16n8k8.row.col.f32.tf32.tf32.f32 "
        "{%0,%1,%2,%3}, {%4,%5,%6,%7}, {%8,%9}, {%0,%1,%2,%3};"
        : "+f"(c0), "+f"(c1), "+f"(c2), "+f"(c3)
        : "r"(a0), "r"(a1), "r"(a2), "r"(a3), "r"(b0), "r"(b1));
}

__device__ __forceinline__ void cp16(uint32_t saddr, const void* gaddr) {
    asm volatile("cp.async.ca.shared.global [%0], [%1], 16;"
                 :: "r"(saddr), "l"(gaddr));
}
#define CP_COMMIT() asm volatile("cp.async.commit_group;")
#define CP_WAIT0()  asm volatile("cp.async.wait_group 0;")

// ---------------------------------------------------------------------------
// Fused projection GEMM (tf32 tensor cores):
// [16384,1024] x [1024, 64x3] -> g_q, g_k, g_v (tf32-rounded on store)
// Block: 128 rows x 192 cols, 256 threads = 8 warps (2x4), warp tile 64x48.
// ---------------------------------------------------------------------------
#define XS_PAD 20
#define WS_PAD 200

__global__ __launch_bounds__(256) void proj_mma_kernel(
    const float* __restrict__ x,
    const float* __restrict__ Wq,
    const float* __restrict__ Wk,
    const float* __restrict__ Wv)
{
    __shared__ float xs[128 * XS_PAD];
    __shared__ float ws[16 * WS_PAD];

    const int tid  = threadIdx.x;
    const int lane = tid & 31;
    const int warp = tid >> 5;
    const int wm = warp >> 2;
    const int wn = warp & 3;
    const int row0 = blockIdx.x * 128;

    float c[4][6][4];
#pragma unroll
    for (int mt = 0; mt < 4; mt++)
#pragma unroll
        for (int nt = 0; nt < 6; nt++)
#pragma unroll
            for (int f = 0; f < 4; f++) c[mt][nt][f] = 0.f;

    const int xr = tid >> 2;
    const int xk4 = (tid & 3) * 4;
    const int wkr = tid >> 4;
    const int wnc = (tid & 15) * 4;

    float4 px0, px1, pw0, pw1, pw2;

    {
        px0 = *(const float4*)&x[(size_t)(row0 + xr) * DIN + 0 + xk4];
        px1 = *(const float4*)&x[(size_t)(row0 + xr + 64) * DIN + 0 + xk4];
        pw0 = *(const float4*)&Wq[(size_t)(0 + wkr) * HD + wnc];
        pw1 = *(const float4*)&Wk[(size_t)(0 + wkr) * HD + wnc];
        pw2 = *(const float4*)&Wv[(size_t)(0 + wkr) * HD + wnc];
    }
    {
        float* p = &xs[xr * XS_PAD + xk4];
        p[0] = f2tf32f(px0.x); p[1] = f2tf32f(px0.y); p[2] = f2tf32f(px0.z); p[3] = f2tf32f(px0.w);
        p = &xs[(xr + 64) * XS_PAD + xk4];
        p[0] = f2tf32f(px1.x); p[1] = f2tf32f(px1.y); p[2] = f2tf32f(px1.z); p[3] = f2tf32f(px1.w);
        p = &ws[wkr * WS_PAD + 0 + wnc];
        p[0] = f2tf32f(pw0.x); p[1] = f2tf32f(pw0.y); p[2] = f2tf32f(pw0.z); p[3] = f2tf32f(pw0.w);
        p = &ws[wkr * WS_PAD + 64 + wnc];
        p[0] = f2tf32f(pw1.x); p[1] = f2tf32f(pw1.y); p[2] = f2tf32f(pw1.z); p[3] = f2tf32f(pw1.w);
        p = &ws[wkr * WS_PAD + 128 + wnc];
        p[0] = f2tf32f(pw2.x); p[1] = f2tf32f(pw2.y); p[2] = f2tf32f(pw2.z); p[3] = f2tf32f(pw2.w);
    }
    __syncthreads();

    for (int kt = 0; kt < 64; kt++) {
        if (kt < 63) {
            const int k0n = (kt + 1) * 16;
            px0 = *(const float4*)&x[(size_t)(row0 + xr) * DIN + k0n + xk4];
            px1 = *(const float4*)&x[(size_t)(row0 + xr + 64) * DIN + k0n + xk4];
            pw0 = *(const float4*)&Wq[(size_t)(k0n + wkr) * HD + wnc];
            pw1 = *(const float4*)&Wk[(size_t)(k0n + wkr) * HD + wnc];
            pw2 = *(const float4*)&Wv[(size_t)(k0n + wkr) * HD + wnc];
        }

#pragma unroll
        for (int ks = 0; ks < 2; ks++) {
            const int kc = ks * 8 + (lane & 3);
            uint32_t a[4][4];
#pragma unroll
            for (int mt = 0; mt < 4; mt++) {
                const int rb = wm * 64 + mt * 16 + (lane >> 2);
                a[mt][0] = __float_as_uint(xs[rb * XS_PAD + kc]);
                a[mt][1] = __float_as_uint(xs[(rb + 8) * XS_PAD + kc]);
                a[mt][2] = __float_as_uint(xs[rb * XS_PAD + kc + 4]);
                a[mt][3] = __float_as_uint(xs[(rb + 8) * XS_PAD + kc + 4]);
            }
#pragma unroll
            for (int nt = 0; nt < 6; nt++) {
                const int nb = wn * 48 + nt * 8 + (lane >> 2);
                uint32_t b0 = __float_as_uint(ws[kc * WS_PAD + nb]);
                uint32_t b1 = __float_as_uint(ws[(kc + 4) * WS_PAD + nb]);
#pragma unroll
                for (int mt = 0; mt < 4; mt++)
                    mma_tf32(c[mt][nt][0], c[mt][nt][1], c[mt][nt][2], c[mt][nt][3],
                             a[mt][0], a[mt][1], a[mt][2], a[mt][3], b0, b1);
            }
        }
        __syncthreads();
        if (kt < 63) {
            float* p = &xs[xr * XS_PAD + xk4];
            p[0] = f2tf32f(px0.x); p[1] = f2tf32f(px0.y); p[2] = f2tf32f(px0.z); p[3] = f2tf32f(px0.w);
            p = &xs[(xr + 64) * XS_PAD + xk4];
            p[0] = f2tf32f(px1.x); p[1] = f2tf32f(px1.y); p[2] = f2tf32f(px1.z); p[3] = f2tf32f(px1.w);
            p = &ws[wkr * WS_PAD + 0 + wnc];
            p[0] = f2tf32f(pw0.x); p[1] = f2tf32f(pw0.y); p[2] = f2tf32f(pw0.z); p[3] = f2tf32f(pw0.w);
            p = &ws[wkr * WS_PAD + 64 + wnc];
            p[0] = f2tf32f(pw1.x); p[1] = f2tf32f(pw1.y); p[2] = f2tf32f(pw1.z); p[3] = f2tf32f(pw1.w);
            p = &ws[wkr * WS_PAD + 128 + wnc];
            p[0] = f2tf32f(pw2.x); p[1] = f2tf32f(pw2.y); p[2] = f2tf32f(pw2.z); p[3] = f2tf32f(pw2.w);
            __syncthreads();
        }
    }

    // epilogue: tf32-round and scatter to g_q/g_k/g_v
#pragma unroll
    for (int mt = 0; mt < 4; mt++) {
        const int row = row0 + wm * 64 + mt * 16 + (lane >> 2);
#pragma unroll
        for (int nt = 0; nt < 6; nt++) {
            const int gcol = wn * 48 + nt * 8 + (lane & 3) * 2;
            float* op = (gcol < 64) ? g_q : ((gcol < 128) ? g_k : g_v);
            const int lcol = gcol & 63;
            *(float2*)&op[(size_t)row * HD + lcol] =
                make_float2(f2tf32f(c[mt][nt][0]), f2tf32f(c[mt][nt][1]));
            *(float2*)&op[(size_t)(row + 8) * HD + lcol] =
                make_float2(f2tf32f(c[mt][nt][2]), f2tf32f(c[mt][nt][3]));
        }
    }
}

// ---------------------------------------------------------------------------
// Flash attention on tensor cores (tf32 mma), swapped roles:
// S[t][s] = (K[t].Q[s])/8, causal s<=t, softmax over s, O[t] = sum_s P V[s].
// Block: 64 t-rows (ONE tile), 128 threads = 4 warps, warp = 16 rows x 64 cols.
// Grid = 256 blocks; schedule maps blockIdx so wave-1 (L<148) gets heavy tiles
// descending and wave-2 (same SM via bid%148) gets light tiles ascending:
// per-SM pair work ~33 steps constant, 2 CTAs/SM resident (smem 92KB/block).
// q-tile prefetched into qs right after GEMM1's barrier; v double-buffered.
// ---------------------------------------------------------------------------
#define APAD 72
#define ATTN_SMEM_FLOATS (5 * 64 * APAD)
#define ATTN_SMEM_BYTES  (ATTN_SMEM_FLOATS * 4)

__global__ __launch_bounds__(128) void attn_mma_kernel(float* __restrict__ out)
{
    extern __shared__ float sm[];
    float* ks  = sm;                   // [t][h]
    float* qs  = ks + 64 * APAD;       // [s][h]
    float* vs0 = qs + 64 * APAD;       // [s][d] buffer 0
    float* vs1 = vs0 + 64 * APAD;      // [s][d] buffer 1
    float* ps  = vs1 + 64 * APAD;      // [t][s] probs (warp-private bands)

    const uint32_t sm_u  = (uint32_t)__cvta_generic_to_shared(sm);
    const uint32_t ks_u  = sm_u;
    const uint32_t qs_u  = sm_u + 64 * APAD * 4;
    const uint32_t vs0_u = qs_u + 64 * APAD * 4;
    const uint32_t vs1_u = vs0_u + 64 * APAD * 4;

    // balanced schedule: d in [0,256); heavy tiles first for wave-1
    const int L = blockIdx.x;
    const int d = (L < 148) ? L : (403 - L);
    const int b = d & 7;
    const int tile = 31 - (d >> 3);
    const int t0 = tile * 64;

    const int tid = threadIdx.x;
    const int lane = tid & 31;
    const int warp = tid >> 5;
    const int j = lane & 3;
    const int r = lane >> 2;
    const size_t bbase = (size_t)b * TLEN;
    const int wr0 = warp * 16;

    // staging indices (8 x 16B per thread per 64x64 tile)
    const int str = tid >> 4;              // +8 per iteration chunk? no: idx pattern below
    (void)str;

    // prologue: K tile + q/v tile for s0=0
    {
        const float* gk = g_k + (bbase + t0) * HD;
        const float* gq = g_q + bbase * HD;
        const float* gv = g_v + bbase * HD;
#pragma unroll
        for (int i = 0; i < 8; i++) {
            const int idx = tid + i * 128;
            const int sr = idx >> 4, h4 = (idx & 15) * 4;
            const uint32_t soff = (sr * APAD + h4) * 4;
            cp16(ks_u + soff,  gk + sr * HD + h4);
            cp16(qs_u + soff,  gq + sr * HD + h4);
            cp16(vs0_u + soff, gv + sr * HD + h4);
        }
        CP_COMMIT();
    }

    float o[8][4];
#pragma unroll
    for (int nt = 0; nt < 8; nt++)
#pragma unroll
        for (int f = 0; f < 4; f++) o[nt][f] = 0.f;
    float m0 = -1e30f, m1 = -1e30f, l0 = 0.f, l1 = 0.f;

    const int rowg0 = t0 + wr0 + r;
    const int rowg1 = rowg0 + 8;

    int buf = 0;
    for (int s0 = 0; s0 <= t0; s0 += 64, buf ^= 1) {
        CP_WAIT0();
        __syncthreads();   // staged q/v ready; all warps past previous step

        // ---- GEMM1: S = K . Q^T ----
        float s[8][4];
#pragma unroll
        for (int nt = 0; nt < 8; nt++)
#pragma unroll
            for (int f = 0; f < 4; f++) s[nt][f] = 0.f;

#pragma unroll
        for (int kk = 0; kk < 8; kk++) {
            const int kc = kk * 8 + j;
            uint32_t a0 = __float_as_uint(ks[(wr0 + r) * APAD + kc]);
            uint32_t a1 = __float_as_uint(ks[(wr0 + r + 8) * APAD + kc]);
            uint32_t a2 = __float_as_uint(ks[(wr0 + r) * APAD + kc + 4]);
            uint32_t a3 = __float_as_uint(ks[(wr0 + r + 8) * APAD + kc + 4]);
#pragma unroll
            for (int nt = 0; nt < 8; nt++) {
                uint32_t b0 = __float_as_uint(qs[(nt * 8 + r) * APAD + kc]);
                uint32_t b1 = __float_as_uint(qs[(nt * 8 + r) * APAD + kc + 4]);
                mma_tf32(s[nt][0], s[nt][1], s[nt][2], s[nt][3], a0, a1, a2, a3, b0, b1);
            }
        }
        __syncthreads();   // qs fully consumed by all warps

        // prefetch next q into qs, next v into the other buffer
        if (s0 < t0) {
            const float* gqn = g_q + (bbase + s0 + 64) * HD;
            const float* gvn = g_v + (bbase + s0 + 64) * HD;
            const uint32_t vn_u = buf ? vs0_u : vs1_u;
#pragma unroll
            for (int i = 0; i < 8; i++) {
                const int idx = tid + i * 128;
                const int sr = idx >> 4, h4 = (idx & 15) * 4;
                const uint32_t soff = (sr * APAD + h4) * 4;
                cp16(qs_u + soff, gqn + sr * HD + h4);
                cp16(vn_u + soff, gvn + sr * HD + h4);
            }
            CP_COMMIT();
        }

        // ---- scale + causal mask + online softmax (rows warp-local) ----
        const bool diag = (s0 == t0);
        float mx0 = -1e30f, mx1 = -1e30f;
#pragma unroll
        for (int nt = 0; nt < 8; nt++) {
            const int cg = s0 + nt * 8 + 2 * j;
            float v0 = s[nt][0] * 0.125f;
            float v1 = s[nt][1] * 0.125f;
            float v2 = s[nt][2] * 0.125f;
            float v3 = s[nt][3] * 0.125f;
            if (diag) {
                if (cg     > rowg0) v0 = -1e30f;
                if (cg + 1 > rowg0) v1 = -1e30f;
                if (cg     > rowg1) v2 = -1e30f;
                if (cg + 1 > rowg1) v3 = -1e30f;
            }
            s[nt][0] = v0; s[nt][1] = v1; s[nt][2] = v2; s[nt][3] = v3;
            mx0 = fmaxf(mx0, fmaxf(v0, v1));
            mx1 = fmaxf(mx1, fmaxf(v2, v3));
        }
        mx0 = fmaxf(mx0, __shfl_xor_sync(0xffffffffu, mx0, 1));
        mx0 = fmaxf(mx0, __shfl_xor_sync(0xffffffffu, mx0, 2));
        mx1 = fmaxf(mx1, __shfl_xor_sync(0xffffffffu, mx1, 1));
        mx1 = fmaxf(mx1, __shfl_xor_sync(0xffffffffu, mx1, 2));

        const float mn0 = fmaxf(m0, mx0);
        const float mn1 = fmaxf(m1, mx1);
        const float corr0 = __expf(m0 - mn0);
        const float corr1 = __expf(m1 - mn1);
        m0 = mn0; m1 = mn1;

        float ls0 = 0.f, ls1 = 0.f;
#pragma unroll
        for (int nt = 0; nt < 8; nt++) {
            const float p0 = f2tf32f(__expf(s[nt][0] - mn0));
            const float p1 = f2tf32f(__expf(s[nt][1] - mn0));
            const float p2 = f2tf32f(__expf(s[nt][2] - mn1));
            const float p3 = f2tf32f(__expf(s[nt][3] - mn1));
            ls0 += p0 + p1;
            ls1 += p2 + p3;
            *(float2*)&ps[(wr0 + r) * APAD + nt * 8 + 2 * j]     = make_float2(p0, p1);
            *(float2*)&ps[(wr0 + r + 8) * APAD + nt * 8 + 2 * j] = make_float2(p2, p3);
        }
        ls0 += __shfl_xor_sync(0xffffffffu, ls0, 1);
        ls0 += __shfl_xor_sync(0xffffffffu, ls0, 2);
        ls1 += __shfl_xor_sync(0xffffffffu, ls1, 1);
        ls1 += __shfl_xor_sync(0xffffffffu, ls1, 2);
        l0 = l0 * corr0 + ls0;
        l1 = l1 * corr1 + ls1;

#pragma unroll
        for (int nt = 0; nt < 8; nt++) {
            o[nt][0] *= corr0; o[nt][1] *= corr0;
            o[nt][2] *= corr1; o[nt][3] *= corr1;
        }
        __syncwarp();   // ps band visible within warp

        // ---- GEMM2: O += P . V ----
        const float* vsb = buf ? vs1 : vs0;
#pragma unroll
        for (int kk = 0; kk < 8; kk++) {
            const int kc = kk * 8 + j;
            uint32_t a0 = __float_as_uint(ps[(wr0 + r) * APAD + kc]);
            uint32_t a1 = __float_as_uint(ps[(wr0 + r + 8) * APAD + kc]);
            uint32_t a2 = __float_as_uint(ps[(wr0 + r) * APAD + kc + 4]);
            uint32_t a3 = __float_as_uint(ps[(wr0 + r + 8) * APAD + kc + 4]);
#pragma unroll
            for (int nt = 0; nt < 8; nt++) {
                uint32_t b0 = __float_as_uint(vsb[kc * APAD + nt * 8 + r]);
                uint32_t b1 = __float_as_uint(vsb[(kc + 4) * APAD + nt * 8 + r]);
                mma_tf32(o[nt][0], o[nt][1], o[nt][2], o[nt][3], a0, a1, a2, a3, b0, b1);
            }
        }
    }

    // epilogue
    const float inv0 = 1.f / l0;
    const float inv1 = 1.f / l1;
    float* op = out + (bbase + t0 + wr0) * HD;
#pragma unroll
    for (int nt = 0; nt < 8; nt++) {
        const int col = nt * 8 + 2 * j;
        *(float2*)&op[r * HD + col] =
            make_float2(o[nt][0] * inv0, o[nt][1] * inv0);
        *(float2*)&op[(r + 8) * HD + col] =
            make_float2(o[nt][2] * inv1, o[nt][3] * inv1);
    }
}

extern "C" void kernel_launch(void* const* d_in, const int* in_sizes, int n_in,
                              void* d_out, int out_size)
{
    const float* x  = (const float*)d_in[0];
    const float* Wq = (const float*)d_in[1];
    const float* Wk = (const float*)d_in[2];
    const float* Wv = (const float*)d_in[3];
    float* out = (float*)d_out;

    cudaFuncSetAttribute(attn_mma_kernel, cudaFuncAttributeMaxDynamicSharedMemorySize,
                         ATTN_SMEM_BYTES);

    proj_mma_kernel<<<BT / 128, 256>>>(x, Wq, Wk, Wv);
    attn_mma_kernel<<<256, 128, ATTN_SMEM_BYTES>>>(out);
}

// round 9
// speedup vs baseline: 1.1124x; 1.1124x over previous
#include <cuda_runtime.h>
#include <cstdint>
#include <cstddef>

#define BATCH 8
#define TLEN 2048
#define DIN 1024
#define HD 64
#define BT (BATCH*TLEN)

// Scratch for projections (no cudaMalloc allowed). Stored pre-rounded to tf32.
// g_v is stored TRANSPOSED: g_vT[b][h][t]
__device__ float g_q[BT*HD];
__device__ float g_k[BT*HD];
__device__ float g_vT[BT*HD];

// ---------------------------------------------------------------------------
// tf32 / mma / cp.async / ldmatrix / f32x2 helpers
// ---------------------------------------------------------------------------
__device__ __forceinline__ uint32_t f2tf32(float f) {
    uint32_t u;
    asm("cvt.rna.tf32.f32 %0, %1;" : "=r"(u) : "f"(f));
    return u;
}
__device__ __forceinline__ float f2tf32f(float f) {
    return __uint_as_float(f2tf32(f));
}

__device__ __forceinline__ void mma_tf32(
    float& c0, float& c1, float& c2, float& c3,
    uint32_t a0, uint32_t a1, uint32_t a2, uint32_t a3,
    uint32_t b0, uint32_t b1)
{
    asm volatile(
        "mma.sync.aligned.m16n8k8.row.col.f32.tf32.tf32.f32 "
        "{%0,%1,%2,%3}, {%4,%5,%6,%7}, {%8,%9}, {%0,%1,%2,%3};"
        : "+f"(c0), "+f"(c1), "+f"(c2), "+f"(c3)
        : "r"(a0), "r"(a1), "r"(a2), "r"(a3), "r"(b0), "r"(b1));
}

__device__ __forceinline__ void cp16(uint32_t saddr, const void* gaddr) {
    asm volatile("cp.async.ca.shared.global [%0], [%1], 16;"
                 :: "r"(saddr), "l"(gaddr));
}
#define CP_COMMIT() asm volatile("cp.async.commit_group;")
#define CP_WAIT0()  asm volatile("cp.async.wait_group 0;")
#define CP_WAIT1()  asm volatile("cp.async.wait_group 1;")

__device__ __forceinline__ void ldsm_x4(uint32_t& r0, uint32_t& r1,
                                        uint32_t& r2, uint32_t& r3, uint32_t addr) {
    asm volatile("ldmatrix.sync.aligned.m8n8.x4.shared.b16 {%0,%1,%2,%3}, [%4];"
                 : "=r"(r0), "=r"(r1), "=r"(r2), "=r"(r3) : "r"(addr));
}

// packed fp32x2 (Blackwell)
__device__ __forceinline__ uint64_t pk2(float a, float b) {
    uint64_t d; asm("mov.b64 %0, {%1,%2};" : "=l"(d) : "f"(a), "f"(b)); return d;
}
__device__ __forceinline__ void upk2(float& a, float& b, uint64_t d) {
    asm("mov.b64 {%0,%1}, %2;" : "=f"(a), "=f"(b) : "l"(d));
}
__device__ __forceinline__ uint64_t add2(uint64_t a, uint64_t b) {
    uint64_t d; asm("add.rn.f32x2 %0, %1, %2;" : "=l"(d) : "l"(a), "l"(b)); return d;
}
__device__ __forceinline__ uint64_t mul2(uint64_t a, uint64_t b) {
    uint64_t d; asm("mul.rn.f32x2 %0, %1, %2;" : "=l"(d) : "l"(a), "l"(b)); return d;
}
__device__ __forceinline__ uint64_t fma2(uint64_t a, uint64_t b, uint64_t c) {
    uint64_t d; asm("fma.rn.f32x2 %0, %1, %2, %3;" : "=l"(d) : "l"(a), "l"(b), "l"(c)); return d;
}

// exp2(x0), exp2(x1) for x in [-126, 0]: magic-number range reduction + deg-4 poly.
// Entirely on fma/alu pipes (no MUFU).
__device__ __forceinline__ void exp2_pair(float x0, float x1, float& p0, float& p1) {
    const uint64_t MAG  = pk2( 12582912.f,  12582912.f);   // 1.5 * 2^23
    const uint64_t NMAG = pk2(-12582912.f, -12582912.f);
    const uint64_t MONE = pk2(-1.f, -1.f);
    const uint64_t C4 = pk2(0.0096181291f, 0.0096181291f);
    const uint64_t C3 = pk2(0.0555041087f, 0.0555041087f);
    const uint64_t C2 = pk2(0.2402265069f, 0.2402265069f);
    const uint64_t C1 = pk2(0.6931471806f, 0.6931471806f);
    const uint64_t C0 = pk2(1.0f, 1.0f);

    x0 = fmaxf(x0, -126.f);
    x1 = fmaxf(x1, -126.f);
    uint64_t X  = pk2(x0, x1);
    uint64_t FX = add2(X, MAG);          // int(x) in low mantissa bits
    uint64_t N  = add2(FX, NMAG);        // rint(x) as float pair
    uint64_t F  = fma2(N, MONE, X);      // frac in [-0.5, 0.5]
    uint64_t P  = fma2(F, C4, C3);
    P = fma2(F, P, C2);
    P = fma2(F, P, C1);
    P = fma2(F, P, C0);
    uint32_t u0, u1;
    asm("mov.b64 {%0,%1}, %2;" : "=r"(u0), "=r"(u1) : "l"(FX));
    uint32_t s0 = (u0 << 23) + 0x3f800000u;   // 2^n bits
    uint32_t s1 = (u1 << 23) + 0x3f800000u;
    uint64_t S = pk2(__uint_as_float(s0), __uint_as_float(s1));
    uint64_t R = mul2(P, S);
    upk2(p0, p1, R);
}

// ---------------------------------------------------------------------------
// Fused projection GEMM (tf32 tensor cores):
// [16384,1024] x [1024, 64x3] -> g_q, g_k (row-major), g_vT (transposed)
// ---------------------------------------------------------------------------
#define XS_PAD 20
#define WS_PAD 200

__global__ __launch_bounds__(256) void proj_mma_kernel(
    const float* __restrict__ x,
    const float* __restrict__ Wq,
    const float* __restrict__ Wk,
    const float* __restrict__ Wv)
{
    __shared__ float xs[128 * XS_PAD];
    __shared__ float ws[16 * WS_PAD];

    const int tid  = threadIdx.x;
    const int lane = tid & 31;
    const int warp = tid >> 5;
    const int wm = warp >> 2;
    const int wn = warp & 3;
    const int row0 = blockIdx.x * 128;

    float c[4][6][4];
#pragma unroll
    for (int mt = 0; mt < 4; mt++)
#pragma unroll
        for (int nt = 0; nt < 6; nt++)
#pragma unroll
            for (int f = 0; f < 4; f++) c[mt][nt][f] = 0.f;

    const int xr = tid >> 2;
    const int xk4 = (tid & 3) * 4;
    const int wkr = tid >> 4;
    const int wnc = (tid & 15) * 4;

    float4 px0, px1, pw0, pw1, pw2;

    {
        px0 = *(const float4*)&x[(size_t)(row0 + xr) * DIN + 0 + xk4];
        px1 = *(const float4*)&x[(size_t)(row0 + xr + 64) * DIN + 0 + xk4];
        pw0 = *(const float4*)&Wq[(size_t)(0 + wkr) * HD + wnc];
        pw1 = *(const float4*)&Wk[(size_t)(0 + wkr) * HD + wnc];
        pw2 = *(const float4*)&Wv[(size_t)(0 + wkr) * HD + wnc];
    }
    {
        float* p = &xs[xr * XS_PAD + xk4];
        p[0] = f2tf32f(px0.x); p[1] = f2tf32f(px0.y); p[2] = f2tf32f(px0.z); p[3] = f2tf32f(px0.w);
        p = &xs[(xr + 64) * XS_PAD + xk4];
        p[0] = f2tf32f(px1.x); p[1] = f2tf32f(px1.y); p[2] = f2tf32f(px1.z); p[3] = f2tf32f(px1.w);
        p = &ws[wkr * WS_PAD + 0 + wnc];
        p[0] = f2tf32f(pw0.x); p[1] = f2tf32f(pw0.y); p[2] = f2tf32f(pw0.z); p[3] = f2tf32f(pw0.w);
        p = &ws[wkr * WS_PAD + 64 + wnc];
        p[0] = f2tf32f(pw1.x); p[1] = f2tf32f(pw1.y); p[2] = f2tf32f(pw1.z); p[3] = f2tf32f(pw1.w);
        p = &ws[wkr * WS_PAD + 128 + wnc];
        p[0] = f2tf32f(pw2.x); p[1] = f2tf32f(pw2.y); p[2] = f2tf32f(pw2.z); p[3] = f2tf32f(pw2.w);
    }
    __syncthreads();

    for (int kt = 0; kt < 64; kt++) {
        if (kt < 63) {
            const int k0n = (kt + 1) * 16;
            px0 = *(const float4*)&x[(size_t)(row0 + xr) * DIN + k0n + xk4];
            px1 = *(const float4*)&x[(size_t)(row0 + xr + 64) * DIN + k0n + xk4];
            pw0 = *(const float4*)&Wq[(size_t)(k0n + wkr) * HD + wnc];
            pw1 = *(const float4*)&Wk[(size_t)(k0n + wkr) * HD + wnc];
            pw2 = *(const float4*)&Wv[(size_t)(k0n + wkr) * HD + wnc];
        }

#pragma unroll
        for (int ks = 0; ks < 2; ks++) {
            const int kc = ks * 8 + (lane & 3);
            uint32_t a[4][4];
#pragma unroll
            for (int mt = 0; mt < 4; mt++) {
                const int rb = wm * 64 + mt * 16 + (lane >> 2);
                a[mt][0] = __float_as_uint(xs[rb * XS_PAD + kc]);
                a[mt][1] = __float_as_uint(xs[(rb + 8) * XS_PAD + kc]);
                a[mt][2] = __float_as_uint(xs[rb * XS_PAD + kc + 4]);
                a[mt][3] = __float_as_uint(xs[(rb + 8) * XS_PAD + kc + 4]);
            }
#pragma unroll
            for (int nt = 0; nt < 6; nt++) {
                const int nb = wn * 48 + nt * 8 + (lane >> 2);
                uint32_t b0 = __float_as_uint(ws[kc * WS_PAD + nb]);
                uint32_t b1 = __float_as_uint(ws[(kc + 4) * WS_PAD + nb]);
#pragma unroll
                for (int mt = 0; mt < 4; mt++)
                    mma_tf32(c[mt][nt][0], c[mt][nt][1], c[mt][nt][2], c[mt][nt][3],
                             a[mt][0], a[mt][1], a[mt][2], a[mt][3], b0, b1);
            }
        }
        __syncthreads();
        if (kt < 63) {
            float* p = &xs[xr * XS_PAD + xk4];
            p[0] = f2tf32f(px0.x); p[1] = f2tf32f(px0.y); p[2] = f2tf32f(px0.z); p[3] = f2tf32f(px0.w);
            p = &xs[(xr + 64) * XS_PAD + xk4];
            p[0] = f2tf32f(px1.x); p[1] = f2tf32f(px1.y); p[2] = f2tf32f(px1.z); p[3] = f2tf32f(px1.w);
            p = &ws[wkr * WS_PAD + 0 + wnc];
            p[0] = f2tf32f(pw0.x); p[1] = f2tf32f(pw0.y); p[2] = f2tf32f(pw0.z); p[3] = f2tf32f(pw0.w);
            p = &ws[wkr * WS_PAD + 64 + wnc];
            p[0] = f2tf32f(pw1.x); p[1] = f2tf32f(pw1.y); p[2] = f2tf32f(pw1.z); p[3] = f2tf32f(pw1.w);
            p = &ws[wkr * WS_PAD + 128 + wnc];
            p[0] = f2tf32f(pw2.x); p[1] = f2tf32f(pw2.y); p[2] = f2tf32f(pw2.z); p[3] = f2tf32f(pw2.w);
            __syncthreads();
        }
    }

    // epilogue: tf32-round; Q/K row-major, V transposed [b][h][t]
#pragma unroll
    for (int mt = 0; mt < 4; mt++) {
        const int row = row0 + wm * 64 + mt * 16 + (lane >> 2);
        const int vb = row >> 11;
        const int vt = row & (TLEN - 1);
#pragma unroll
        for (int nt = 0; nt < 6; nt++) {
            const int gcol = wn * 48 + nt * 8 + (lane & 3) * 2;
            if (gcol < 128) {
                float* op = (gcol < 64) ? g_q : g_k;
                const int lcol = gcol & 63;
                *(float2*)&op[(size_t)row * HD + lcol] =
                    make_float2(f2tf32f(c[mt][nt][0]), f2tf32f(c[mt][nt][1]));
                *(float2*)&op[(size_t)(row + 8) * HD + lcol] =
                    make_float2(f2tf32f(c[mt][nt][2]), f2tf32f(c[mt][nt][3]));
            } else {
                const int h = gcol - 128;
                float* vp = g_vT + ((size_t)vb * HD + h) * TLEN;
                vp[vt]            = f2tf32f(c[mt][nt][0]);
                vp[TLEN + vt]     = f2tf32f(c[mt][nt][1]);
                vp[vt + 8]        = f2tf32f(c[mt][nt][2]);
                vp[TLEN + vt + 8] = f2tf32f(c[mt][nt][3]);
            }
        }
    }
}

// ---------------------------------------------------------------------------
// Flash attention, tf32 mma, swapped roles. Block = one 64-row tile, 128 thr,
// 4 warps x 16 rows. K fragments live in registers (loaded once, pre-scaled by
// 0.125*log2e). ldmatrix for Q/P/V^T fragments. exp2 via packed-f32 polynomial
// (no MUFU). Double-buffered q & vT, one __syncthreads per step.
// ---------------------------------------------------------------------------
#define APAD 68
#define TILEF (64 * APAD)
#define ATTN_SMEM_FLOATS (5 * TILEF)
#define ATTN_SMEM_BYTES  (ATTN_SMEM_FLOATS * 4)

__global__ __launch_bounds__(128) void attn_mma_kernel(float* __restrict__ out)
{
    extern __shared__ float sm[];
    const uint32_t sm_u = (uint32_t)__cvta_generic_to_shared(sm);
    const uint32_t qs_u[2] = { sm_u,               sm_u + TILEF * 4 };
    const uint32_t vs_u[2] = { sm_u + 2 * TILEF * 4, sm_u + 3 * TILEF * 4 };
    const uint32_t ps_u    = sm_u + 4 * TILEF * 4;

    // balanced schedule: wave-1 (L<148) heavy tiles descending; wave-2 light.
    const int L = blockIdx.x;
    const int d = (L < 148) ? L : (403 - L);
    const int b = d & 7;
    const int tile = 31 - (d >> 3);
    const int t0 = tile * 64;

    const int tid = threadIdx.x;
    const int lane = tid & 31;
    const int warp = tid >> 5;
    const int j = lane & 3;
    const int r = lane >> 2;
    const size_t bbase = (size_t)b * TLEN;
    const int wr0 = warp * 16;

    // ldmatrix per-lane offsets (words)
    const int aoff = ((lane & 7) + (lane & 8)) * APAD + ((lane & 16) >> 2);
    const int boff = ((lane & 7) + ((lane & 16) >> 1)) * APAD + ((lane & 8) >> 1);

    // staging indices
    const int ssr = tid >> 4;            // base row, +8 per chunk... (idx pattern)

    // prologue: K -> ps staging; q0 -> qs0; vT0 -> vs0
    {
        const float* gk = g_k + (bbase + t0) * HD;
        const float* gq = g_q + bbase * HD;
        const float* gv = g_vT + (size_t)b * HD * TLEN;   // rows h, cols t
#pragma unroll
        for (int i = 0; i < 8; i++) {
            const int idx = tid + i * 128;
            const int sr = idx >> 4, c4 = (idx & 15) * 4;
            cp16(ps_u + (sr * APAD + c4) * 4, gk + sr * HD + c4);
        }
        CP_COMMIT();
#pragma unroll
        for (int i = 0; i < 8; i++) {
            const int idx = tid + i * 128;
            const int sr = idx >> 4, c4 = (idx & 15) * 4;
            cp16(qs_u[0] + (sr * APAD + c4) * 4, gq + sr * HD + c4);
            cp16(vs_u[0] + (sr * APAD + c4) * 4, gv + (size_t)sr * TLEN + c4);
        }
        CP_COMMIT();
    }
    (void)ssr;

    // K fragments: wait K group (1 pending allowed = q/v group), sync, ldsm.
    uint32_t kf[8][4];
    CP_WAIT1();
    __syncthreads();
    {
        const float CSC = 0.125f * 1.4426950408889634f;   // fold scale+log2e
#pragma unroll
        for (int kk = 0; kk < 8; kk++) {
            ldsm_x4(kf[kk][0], kf[kk][1], kf[kk][2], kf[kk][3],
                    ps_u + (wr0 * APAD + aoff + kk * 8) * 4);
#pragma unroll
            for (int f = 0; f < 4; f++)
                kf[kk][f] = f2tf32(__uint_as_float(kf[kk][f]) * CSC);
        }
        __syncwarp();   // ps reads done before step-0 softmax rewrites band
    }

    float o[8][4];
#pragma unroll
    for (int nt = 0; nt < 8; nt++)
#pragma unroll
        for (int f = 0; f < 4; f++) o[nt][f] = 0.f;
    float m0 = -1e30f, m1 = -1e30f, l0 = 0.f, l1 = 0.f;

    const int rowg0 = t0 + wr0 + r;
    const int rowg1 = rowg0 + 8;

    int buf = 0;
    for (int s0 = 0; s0 <= t0; s0 += 64, buf ^= 1) {
        CP_WAIT0();
        __syncthreads();   // current buffers staged; all warps done with prev step

        // prefetch next q/vT into alternate buffers (overlaps whole step)
        if (s0 < t0) {
            const float* gqn = g_q + (bbase + s0 + 64) * HD;
            const float* gvn = g_vT + (size_t)b * HD * TLEN + (s0 + 64);
            const int nb = buf ^ 1;
#pragma unroll
            for (int i = 0; i < 8; i++) {
                const int idx = tid + i * 128;
                const int sr = idx >> 4, c4 = (idx & 15) * 4;
                cp16(qs_u[nb] + (sr * APAD + c4) * 4, gqn + sr * HD + c4);
                cp16(vs_u[nb] + (sr * APAD + c4) * 4, gvn + (size_t)sr * TLEN + c4);
            }
            CP_COMMIT();
        }

        // ---- GEMM1: S = (K*CSC) . Q^T  (log2-scaled scores) ----
        float s[8][4];
#pragma unroll
        for (int nt = 0; nt < 8; nt++)
#pragma unroll
            for (int f = 0; f < 4; f++) s[nt][f] = 0.f;

#pragma unroll
        for (int kk = 0; kk < 8; kk++) {
#pragma unroll
            for (int nt2 = 0; nt2 < 4; nt2++) {
                uint32_t b0, b1, b2, b3;
                ldsm_x4(b0, b1, b2, b3,
                        qs_u[buf] + (boff + nt2 * 16 * APAD + kk * 8) * 4);
                mma_tf32(s[nt2*2][0], s[nt2*2][1], s[nt2*2][2], s[nt2*2][3],
                         kf[kk][0], kf[kk][1], kf[kk][2], kf[kk][3], b0, b1);
                mma_tf32(s[nt2*2+1][0], s[nt2*2+1][1], s[nt2*2+1][2], s[nt2*2+1][3],
                         kf[kk][0], kf[kk][1], kf[kk][2], kf[kk][3], b2, b3);
            }
        }

        // ---- causal mask + online softmax (log2 domain, no MUFU for exps) ----
        const bool diag = (s0 == t0);
        float mx0 = -1e30f, mx1 = -1e30f;
#pragma unroll
        for (int nt = 0; nt < 8; nt++) {
            if (diag) {
                const int cg = s0 + nt * 8 + 2 * j;
                if (cg     > rowg0) s[nt][0] = -1e30f;
                if (cg + 1 > rowg0) s[nt][1] = -1e30f;
                if (cg     > rowg1) s[nt][2] = -1e30f;
                if (cg + 1 > rowg1) s[nt][3] = -1e30f;
            }
            mx0 = fmaxf(mx0, fmaxf(s[nt][0], s[nt][1]));
            mx1 = fmaxf(mx1, fmaxf(s[nt][2], s[nt][3]));
        }
        mx0 = fmaxf(mx0, __shfl_xor_sync(0xffffffffu, mx0, 1));
        mx0 = fmaxf(mx0, __shfl_xor_sync(0xffffffffu, mx0, 2));
        mx1 = fmaxf(mx1, __shfl_xor_sync(0xffffffffu, mx1, 1));
        mx1 = fmaxf(mx1, __shfl_xor_sync(0xffffffffu, mx1, 2));

        const float mn0 = fmaxf(m0, mx0);
        const float mn1 = fmaxf(m1, mx1);
        const float corr0 = exp2f(m0 - mn0);
        const float corr1 = exp2f(m1 - mn1);
        m0 = mn0; m1 = mn1;

        float ls0 = 0.f, ls1 = 0.f;
#pragma unroll
        for (int nt = 0; nt < 8; nt++) {
            float p0, p1, p2, p3;
            exp2_pair(s[nt][0] - mn0, s[nt][1] - mn0, p0, p1);
            exp2_pair(s[nt][2] - mn1, s[nt][3] - mn1, p2, p3);
            p0 = f2tf32f(p0); p1 = f2tf32f(p1);
            p2 = f2tf32f(p2); p3 = f2tf32f(p3);
            ls0 += p0 + p1;
            ls1 += p2 + p3;
            float* pr0 = sm + 4 * TILEF + (wr0 + r) * APAD + nt * 8 + 2 * j;
            float* pr1 = sm + 4 * TILEF + (wr0 + r + 8) * APAD + nt * 8 + 2 * j;
            *(float2*)pr0 = make_float2(p0, p1);
            *(float2*)pr1 = make_float2(p2, p3);
        }
        ls0 += __shfl_xor_sync(0xffffffffu, ls0, 1);
        ls0 += __shfl_xor_sync(0xffffffffu, ls0, 2);
        ls1 += __shfl_xor_sync(0xffffffffu, ls1, 1);
        ls1 += __shfl_xor_sync(0xffffffffu, ls1, 2);
        l0 = l0 * corr0 + ls0;
        l1 = l1 * corr1 + ls1;

#pragma unroll
        for (int nt = 0; nt < 8; nt++) {
            o[nt][0] *= corr0; o[nt][1] *= corr0;
            o[nt][2] *= corr1; o[nt][3] *= corr1;
        }
        __syncwarp();   // ps band visible to all lanes of this warp

        // ---- GEMM2: O += P . V  (A = P from ps, B = V^T tile) ----
#pragma unroll
        for (int kk = 0; kk < 8; kk++) {
            uint32_t a0, a1, a2, a3;
            ldsm_x4(a0, a1, a2, a3, ps_u + (wr0 * APAD + aoff + kk * 8) * 4);
#pragma unroll
            for (int nt2 = 0; nt2 < 4; nt2++) {
                uint32_t b0, b1, b2, b3;
                ldsm_x4(b0, b1, b2, b3,
                        vs_u[buf] + (boff + nt2 * 16 * APAD + kk * 8) * 4);
                mma_tf32(o[nt2*2][0], o[nt2*2][1], o[nt2*2][2], o[nt2*2][3],
                         a0, a1, a2, a3, b0, b1);
                mma_tf32(o[nt2*2+1][0], o[nt2*2+1][1], o[nt2*2+1][2], o[nt2*2+1][3],
                         a0, a1, a2, a3, b2, b3);
            }
        }
    }

    // epilogue
    const float inv0 = 1.f / l0;
    const float inv1 = 1.f / l1;
    float* op = out + (bbase + t0 + wr0) * HD;
#pragma unroll
    for (int nt = 0; nt < 8; nt++) {
        const int col = nt * 8 + 2 * j;
        *(float2*)&op[r * HD + col] =
            make_float2(o[nt][0] * inv0, o[nt][1] * inv0);
        *(float2*)&op[(r + 8) * HD + col] =
            make_float2(o[nt][2] * inv1, o[nt][3] * inv1);
    }
}

extern "C" void kernel_launch(void* const* d_in, const int* in_sizes, int n_in,
                              void* d_out, int out_size)
{
    const float* x  = (const float*)d_in[0];
    const float* Wq = (const float*)d_in[1];
    const float* Wk = (const float*)d_in[2];
    const float* Wv = (const float*)d_in[3];
    float* out = (float*)d_out;

    cudaFuncSetAttribute(attn_mma_kernel, cudaFuncAttributeMaxDynamicSharedMemorySize,
                         ATTN_SMEM_BYTES);

    proj_mma_kernel<<<BT / 128, 256>>>(x, Wq, Wk, Wv);
    attn_mma_kernel<<<256, 128, ATTN_SMEM_BYTES>>>(out);
}

// round 13
// speedup vs baseline: 1.2680x; 1.1398x over previous
#include <cuda_runtime.h>
#include <cstdint>
#include <cstddef>

#define BATCH 8
#define TLEN 2048
#define DIN 1024
#define HD 64
#define BT (BATCH*TLEN)

// Scratch for projections (no cudaMalloc allowed). Stored pre-rounded to tf32.
// g_v is stored TRANSPOSED: g_vT[b][h][t]
__device__ float g_q[BT*HD];
__device__ float g_k[BT*HD];
__device__ float g_vT[BT*HD];

// ---------------------------------------------------------------------------
// tf32 / mma / cp.async / ldmatrix / f32x2 helpers
// ---------------------------------------------------------------------------
__device__ __forceinline__ uint32_t f2tf32(float f) {
    uint32_t u;
    asm("cvt.rna.tf32.f32 %0, %1;" : "=r"(u) : "f"(f));
    return u;
}
__device__ __forceinline__ float f2tf32f(float f) {
    return __uint_as_float(f2tf32(f));
}

__device__ __forceinline__ void mma_tf32(
    float& c0, float& c1, float& c2, float& c3,
    uint32_t a0, uint32_t a1, uint32_t a2, uint32_t a3,
    uint32_t b0, uint32_t b1)
{
    asm volatile(
        "mma.sync.aligned.m16n8k8.row.col.f32.tf32.tf32.f32 "
        "{%0,%1,%2,%3}, {%4,%5,%6,%7}, {%8,%9}, {%0,%1,%2,%3};"
        : "+f"(c0), "+f"(c1), "+f"(c2), "+f"(c3)
        : "r"(a0), "r"(a1), "r"(a2), "r"(a3), "r"(b0), "r"(b1));
}

__device__ __forceinline__ void cp16(uint32_t saddr, const void* gaddr) {
    asm volatile("cp.async.ca.shared.global [%0], [%1], 16;"
                 :: "r"(saddr), "l"(gaddr));
}
#define CP_COMMIT() asm volatile("cp.async.commit_group;")
#define CP_WAIT0()  asm volatile("cp.async.wait_group 0;")
#define CP_WAIT1()  asm volatile("cp.async.wait_group 1;")

__device__ __forceinline__ void ldsm_x4(uint32_t& r0, uint32_t& r1,
                                        uint32_t& r2, uint32_t& r3, uint32_t addr) {
    asm volatile("ldmatrix.sync.aligned.m8n8.x4.shared.b16 {%0,%1,%2,%3}, [%4];"
                 : "=r"(r0), "=r"(r1), "=r"(r2), "=r"(r3) : "r"(addr));
}

// packed fp32x2 (Blackwell)
__device__ __forceinline__ uint64_t pk2(float a, float b) {
    uint64_t d; asm("mov.b64 %0, {%1,%2};" : "=l"(d) : "f"(a), "f"(b)); return d;
}
__device__ __forceinline__ void upk2(float& a, float& b, uint64_t d) {
    asm("mov.b64 {%0,%1}, %2;" : "=f"(a), "=f"(b) : "l"(d));
}
__device__ __forceinline__ uint64_t add2(uint64_t a, uint64_t b) {
    uint64_t d; asm("add.rn.f32x2 %0, %1, %2;" : "=l"(d) : "l"(a), "l"(b)); return d;
}
__device__ __forceinline__ uint64_t mul2(uint64_t a, uint64_t b) {
    uint64_t d; asm("mul.rn.f32x2 %0, %1, %2;" : "=l"(d) : "l"(a), "l"(b)); return d;
}
__device__ __forceinline__ uint64_t fma2(uint64_t a, uint64_t b, uint64_t c) {
    uint64_t d; asm("fma.rn.f32x2 %0, %1, %2, %3;" : "=l"(d) : "l"(a), "l"(b), "l"(c)); return d;
}

// exp2(x0), exp2(x1) for x <= 0: magic-number range reduction + deg-4 poly.
// Entirely on fma/alu pipes (no MUFU).
__device__ __forceinline__ void exp2_pair(float x0, float x1, float& p0, float& p1) {
    const uint64_t MAG  = pk2( 12582912.f,  12582912.f);   // 1.5 * 2^23
    const uint64_t NMAG = pk2(-12582912.f, -12582912.f);
    const uint64_t MONE = pk2(-1.f, -1.f);
    const uint64_t C4 = pk2(0.0096181291f, 0.0096181291f);
    const uint64_t C3 = pk2(0.0555041087f, 0.0555041087f);
    const uint64_t C2 = pk2(0.2402265069f, 0.2402265069f);
    const uint64_t C1 = pk2(0.6931471806f, 0.6931471806f);
    const uint64_t C0 = pk2(1.0f, 1.0f);

    x0 = fmaxf(x0, -126.f);
    x1 = fmaxf(x1, -126.f);
    uint64_t X  = pk2(x0, x1);
    uint64_t FX = add2(X, MAG);          // int(x) in low mantissa bits
    uint64_t N  = add2(FX, NMAG);        // rint(x) as float pair
    uint64_t F  = fma2(N, MONE, X);      // frac in [-0.5, 0.5]
    uint64_t P  = fma2(F, C4, C3);
    P = fma2(F, P, C2);
    P = fma2(F, P, C1);
    P = fma2(F, P, C0);
    uint32_t u0, u1;
    asm("mov.b64 {%0,%1}, %2;" : "=r"(u0), "=r"(u1) : "l"(FX));
    uint32_t s0 = (u0 << 23) + 0x3f800000u;   // 2^n bits
    uint32_t s1 = (u1 << 23) + 0x3f800000u;
    uint64_t S = pk2(__uint_as_float(s0), __uint_as_float(s1));
    uint64_t R = mul2(P, S);
    upk2(p0, p1, R);
}

// ---------------------------------------------------------------------------
// Fused projection GEMM (tf32 tensor cores):
// [16384,1024] x [1024, 64x3] -> g_q, g_k (row-major), g_vT (transposed)
// ---------------------------------------------------------------------------
#define XS_PAD 20
#define WS_PAD 200

__global__ __launch_bounds__(256) void proj_mma_kernel(
    const float* __restrict__ x,
    const float* __restrict__ Wq,
    const float* __restrict__ Wk,
    const float* __restrict__ Wv)
{
    __shared__ float xs[128 * XS_PAD];
    __shared__ float ws[16 * WS_PAD];

    const int tid  = threadIdx.x;
    const int lane = tid & 31;
    const int warp = tid >> 5;
    const int wm = warp >> 2;
    const int wn = warp & 3;
    const int row0 = blockIdx.x * 128;

    float c[4][6][4];
#pragma unroll
    for (int mt = 0; mt < 4; mt++)
#pragma unroll
        for (int nt = 0; nt < 6; nt++)
#pragma unroll
            for (int f = 0; f < 4; f++) c[mt][nt][f] = 0.f;

    const int xr = tid >> 2;
    const int xk4 = (tid & 3) * 4;
    const int wkr = tid >> 4;
    const int wnc = (tid & 15) * 4;

    float4 px0, px1, pw0, pw1, pw2;

    {
        px0 = *(const float4*)&x[(size_t)(row0 + xr) * DIN + 0 + xk4];
        px1 = *(const float4*)&x[(size_t)(row0 + xr + 64) * DIN + 0 + xk4];
        pw0 = *(const float4*)&Wq[(size_t)(0 + wkr) * HD + wnc];
        pw1 = *(const float4*)&Wk[(size_t)(0 + wkr) * HD + wnc];
        pw2 = *(const float4*)&Wv[(size_t)(0 + wkr) * HD + wnc];
    }
    {
        float* p = &xs[xr * XS_PAD + xk4];
        p[0] = f2tf32f(px0.x); p[1] = f2tf32f(px0.y); p[2] = f2tf32f(px0.z); p[3] = f2tf32f(px0.w);
        p = &xs[(xr + 64) * XS_PAD + xk4];
        p[0] = f2tf32f(px1.x); p[1] = f2tf32f(px1.y); p[2] = f2tf32f(px1.z); p[3] = f2tf32f(px1.w);
        p = &ws[wkr * WS_PAD + 0 + wnc];
        p[0] = f2tf32f(pw0.x); p[1] = f2tf32f(pw0.y); p[2] = f2tf32f(pw0.z); p[3] = f2tf32f(pw0.w);
        p = &ws[wkr * WS_PAD + 64 + wnc];
        p[0] = f2tf32f(pw1.x); p[1] = f2tf32f(pw1.y); p[2] = f2tf32f(pw1.z); p[3] = f2tf32f(pw1.w);
        p = &ws[wkr * WS_PAD + 128 + wnc];
        p[0] = f2tf32f(pw2.x); p[1] = f2tf32f(pw2.y); p[2] = f2tf32f(pw2.z); p[3] = f2tf32f(pw2.w);
    }
    __syncthreads();

    for (int kt = 0; kt < 64; kt++) {
        if (kt < 63) {
            const int k0n = (kt + 1) * 16;
            px0 = *(const float4*)&x[(size_t)(row0 + xr) * DIN + k0n + xk4];
            px1 = *(const float4*)&x[(size_t)(row0 + xr + 64) * DIN + k0n + xk4];
            pw0 = *(const float4*)&Wq[(size_t)(k0n + wkr) * HD + wnc];
            pw1 = *(const float4*)&Wk[(size_t)(k0n + wkr) * HD + wnc];
            pw2 = *(const float4*)&Wv[(size_t)(k0n + wkr) * HD + wnc];
        }

#pragma unroll
        for (int ks = 0; ks < 2; ks++) {
            const int kc = ks * 8 + (lane & 3);
            uint32_t a[4][4];
#pragma unroll
            for (int mt = 0; mt < 4; mt++) {
                const int rb = wm * 64 + mt * 16 + (lane >> 2);
                a[mt][0] = __float_as_uint(xs[rb * XS_PAD + kc]);
                a[mt][1] = __float_as_uint(xs[(rb + 8) * XS_PAD + kc]);
                a[mt][2] = __float_as_uint(xs[rb * XS_PAD + kc + 4]);
                a[mt][3] = __float_as_uint(xs[(rb + 8) * XS_PAD + kc + 4]);
            }
#pragma unroll
            for (int nt = 0; nt < 6; nt++) {
                const int nb = wn * 48 + nt * 8 + (lane >> 2);
                uint32_t b0 = __float_as_uint(ws[kc * WS_PAD + nb]);
                uint32_t b1 = __float_as_uint(ws[(kc + 4) * WS_PAD + nb]);
#pragma unroll
                for (int mt = 0; mt < 4; mt++)
                    mma_tf32(c[mt][nt][0], c[mt][nt][1], c[mt][nt][2], c[mt][nt][3],
                             a[mt][0], a[mt][1], a[mt][2], a[mt][3], b0, b1);
            }
        }
        __syncthreads();
        if (kt < 63) {
            float* p = &xs[xr * XS_PAD + xk4];
            p[0] = f2tf32f(px0.x); p[1] = f2tf32f(px0.y); p[2] = f2tf32f(px0.z); p[3] = f2tf32f(px0.w);
            p = &xs[(xr + 64) * XS_PAD + xk4];
            p[0] = f2tf32f(px1.x); p[1] = f2tf32f(px1.y); p[2] = f2tf32f(px1.z); p[3] = f2tf32f(px1.w);
            p = &ws[wkr * WS_PAD + 0 + wnc];
            p[0] = f2tf32f(pw0.x); p[1] = f2tf32f(pw0.y); p[2] = f2tf32f(pw0.z); p[3] = f2tf32f(pw0.w);
            p = &ws[wkr * WS_PAD + 64 + wnc];
            p[0] = f2tf32f(pw1.x); p[1] = f2tf32f(pw1.y); p[2] = f2tf32f(pw1.z); p[3] = f2tf32f(pw1.w);
            p = &ws[wkr * WS_PAD + 128 + wnc];
            p[0] = f2tf32f(pw2.x); p[1] = f2tf32f(pw2.y); p[2] = f2tf32f(pw2.z); p[3] = f2tf32f(pw2.w);
            __syncthreads();
        }
    }

    // epilogue: tf32-round; Q/K row-major, V transposed [b][h][t]
#pragma unroll
    for (int mt = 0; mt < 4; mt++) {
        const int row = row0 + wm * 64 + mt * 16 + (lane >> 2);
        const int vb = row >> 11;
        const int vt = row & (TLEN - 1);
#pragma unroll
        for (int nt = 0; nt < 6; nt++) {
            const int gcol = wn * 48 + nt * 8 + (lane & 3) * 2;
            if (gcol < 128) {
                float* op = (gcol < 64) ? g_q : g_k;
                const int lcol = gcol & 63;
                *(float2*)&op[(size_t)row * HD + lcol] =
                    make_float2(f2tf32f(c[mt][nt][0]), f2tf32f(c[mt][nt][1]));
                *(float2*)&op[(size_t)(row + 8) * HD + lcol] =
                    make_float2(f2tf32f(c[mt][nt][2]), f2tf32f(c[mt][nt][3]));
            } else {
                const int h = gcol - 128;
                float* vp = g_vT + ((size_t)vb * HD + h) * TLEN;
                vp[vt]            = f2tf32f(c[mt][nt][0]);
                vp[TLEN + vt]     = f2tf32f(c[mt][nt][1]);
                vp[vt + 8]        = f2tf32f(c[mt][nt][2]);
                vp[TLEN + vt + 8] = f2tf32f(c[mt][nt][3]);
            }
        }
    }
}

// ---------------------------------------------------------------------------
// Flash attention, tf32 mma throughout (precision floor: softmax-weighted
// output rel_err ~= operand epsilon, so GEMM2 must be tf32+). K frags in regs
// (pre-scaled by 0.125*log2e), exp2 via packed-f32 poly (no MUFU).
// Single-buffered V + double-buffered Q: smem 69.6KB -> 3 CTAs/SM.
// Pipeline per step: WAIT(q_i); barA; issue v_i + q_{i+1}; GEMM1; softmax;
// WAIT(v_i); barB; GEMM2.  v_i flight overlaps GEMM1+softmax.
// ---------------------------------------------------------------------------
#define APAD 68
#define TILEF (64 * APAD)
#define ATTN_SMEM_FLOATS (4 * TILEF)
#define ATTN_SMEM_BYTES  (ATTN_SMEM_FLOATS * 4)   // 69632

__global__ __launch_bounds__(128, 3) void attn_mma_kernel(float* __restrict__ out)
{
    extern __shared__ float sm[];
    const uint32_t sm_u = (uint32_t)__cvta_generic_to_shared(sm);
    const uint32_t qs_u[2] = { sm_u, sm_u + TILEF * 4 };
    const uint32_t vs_u    = sm_u + 2 * TILEF * 4;
    const uint32_t ps_u    = sm_u + 3 * TILEF * 4;
    float* psf = sm + 3 * TILEF;

    // schedule: SM pair (L, L+148) heavy+light; all 256 blocks co-resident.
    const int L = blockIdx.x;
    const int d = (L < 148) ? L : (403 - L);
    const int b = d & 7;
    const int tile = 31 - (d >> 3);
    const int t0 = tile * 64;

    const int tid = threadIdx.x;
    const int lane = tid & 31;
    const int warp = tid >> 5;
    const int j = lane & 3;
    const int r = lane >> 2;
    const size_t bbase = (size_t)b * TLEN;
    const int wr0 = warp * 16;

    // ldmatrix per-lane offsets (words)
    const int aoff = ((lane & 7) + (lane & 8)) * APAD + ((lane & 16) >> 2);
    const int boff = ((lane & 7) + ((lane & 16) >> 1)) * APAD + ((lane & 8) >> 1);

    const float* gvb = g_vT + (size_t)b * HD * TLEN;   // [h][t]

    // prologue: K -> ps staging (group); q0 -> qs[0] (group)
    {
        const float* gk = g_k + (bbase + t0) * HD;
        const float* gq = g_q + bbase * HD;
#pragma unroll
        for (int i = 0; i < 8; i++) {
            const int idx = tid + i * 128;
            const int sr = idx >> 4, c4 = (idx & 15) * 4;
            cp16(ps_u + (sr * APAD + c4) * 4, gk + sr * HD + c4);
        }
        CP_COMMIT();
#pragma unroll
        for (int i = 0; i < 8; i++) {
            const int idx = tid + i * 128;
            const int sr = idx >> 4, c4 = (idx & 15) * 4;
            cp16(qs_u[0] + (sr * APAD + c4) * 4, gq + sr * HD + c4);
        }
        CP_COMMIT();
    }

    // K fragments: wait K group only (q0 may pend), sync, ldsm, pre-scale.
    uint32_t kf[8][4];
    CP_WAIT1();
    __syncthreads();
    {
        const float CSC = 0.125f * 1.4426950408889634f;   // fold 64^-0.5 and log2e
#pragma unroll
        for (int kk = 0; kk < 8; kk++) {
            ldsm_x4(kf[kk][0], kf[kk][1], kf[kk][2], kf[kk][3],
                    ps_u + (wr0 * APAD + aoff + kk * 8) * 4);
#pragma unroll
            for (int f = 0; f < 4; f++)
                kf[kk][f] = f2tf32(__uint_as_float(kf[kk][f]) * CSC);
        }
        // ps reads are warp-private (own band); softmax writes are too.
    }

    float o[8][4];
#pragma unroll
    for (int nt = 0; nt < 8; nt++)
#pragma unroll
        for (int f = 0; f < 4; f++) o[nt][f] = 0.f;
    float m0 = -1e30f, m1 = -1e30f, l0 = 0.f, l1 = 0.f;

    const int rowg0 = t0 + wr0 + r;
    const int rowg1 = rowg0 + 8;

    int buf = 0;
    for (int s0 = 0; s0 <= t0; s0 += 64, buf ^= 1) {
        CP_WAIT0();        // q_i arrived (v_{i-1} already waited at barB)
        __syncthreads();   // barA: q_i visible; all warps done GEMM2(i-1) (vs
                           // free) and GEMM1(i-1) (qs[buf^1] free)

        // issue v_i into the single V buffer (overlaps GEMM1 + softmax)
        {
            const float* gv = gvb + s0;
#pragma unroll
            for (int i = 0; i < 8; i++) {
                const int idx = tid + i * 128;
                const int sr = idx >> 4, c4 = (idx & 15) * 4;
                cp16(vs_u + (sr * APAD + c4) * 4, gv + (size_t)sr * TLEN + c4);
            }
            CP_COMMIT();
        }
        // issue q_{i+1}
        if (s0 < t0) {
            const float* gqn = g_q + (bbase + s0 + 64) * HD;
#pragma unroll
            for (int i = 0; i < 8; i++) {
                const int idx = tid + i * 128;
                const int sr = idx >> 4, c4 = (idx & 15) * 4;
                cp16(qs_u[buf ^ 1] + (sr * APAD + c4) * 4, gqn + sr * HD + c4);
            }
            CP_COMMIT();
        }

        // ---- GEMM1: S = (K*CSC) . Q^T  (log2-scaled scores) ----
        float s[8][4];
#pragma unroll
        for (int nt = 0; nt < 8; nt++)
#pragma unroll
            for (int f = 0; f < 4; f++) s[nt][f] = 0.f;

#pragma unroll
        for (int kk = 0; kk < 8; kk++) {
#pragma unroll
            for (int nt2 = 0; nt2 < 4; nt2++) {
                uint32_t b0, b1, b2, b3;
                ldsm_x4(b0, b1, b2, b3,
                        qs_u[buf] + (boff + nt2 * 16 * APAD + kk * 8) * 4);
                mma_tf32(s[nt2*2][0], s[nt2*2][1], s[nt2*2][2], s[nt2*2][3],
                         kf[kk][0], kf[kk][1], kf[kk][2], kf[kk][3], b0, b1);
                mma_tf32(s[nt2*2+1][0], s[nt2*2+1][1], s[nt2*2+1][2], s[nt2*2+1][3],
                         kf[kk][0], kf[kk][1], kf[kk][2], kf[kk][3], b2, b3);
            }
        }

        // ---- causal mask + online softmax (log2 domain, no MUFU) ----
        const bool diag = (s0 == t0);
        float mx0 = -1e30f, mx1 = -1e30f;
#pragma unroll
        for (int nt = 0; nt < 8; nt++) {
            if (diag) {
                const int cg = s0 + nt * 8 + 2 * j;
                if (cg     > rowg0) s[nt][0] = -1e30f;
                if (cg + 1 > rowg0) s[nt][1] = -1e30f;
                if (cg     > rowg1) s[nt][2] = -1e30f;
                if (cg + 1 > rowg1) s[nt][3] = -1e30f;
            }
            mx0 = fmaxf(mx0, fmaxf(s[nt][0], s[nt][1]));
            mx1 = fmaxf(mx1, fmaxf(s[nt][2], s[nt][3]));
        }
        mx0 = fmaxf(mx0, __shfl_xor_sync(0xffffffffu, mx0, 1));
        mx0 = fmaxf(mx0, __shfl_xor_sync(0xffffffffu, mx0, 2));
        mx1 = fmaxf(mx1, __shfl_xor_sync(0xffffffffu, mx1, 1));
        mx1 = fmaxf(mx1, __shfl_xor_sync(0xffffffffu, mx1, 2));

        const float mn0 = fmaxf(m0, mx0);
        const float mn1 = fmaxf(m1, mx1);
        const float corr0 = exp2f(m0 - mn0);
        const float corr1 = exp2f(m1 - mn1);
        m0 = mn0; m1 = mn1;

        float ls0 = 0.f, ls1 = 0.f;
#pragma unroll
        for (int nt = 0; nt < 8; nt++) {
            float p0, p1, p2, p3;
            exp2_pair(s[nt][0] - mn0, s[nt][1] - mn0, p0, p1);
            exp2_pair(s[nt][2] - mn1, s[nt][3] - mn1, p2, p3);
            p0 = f2tf32f(p0); p1 = f2tf32f(p1);
            p2 = f2tf32f(p2); p3 = f2tf32f(p3);
            ls0 += p0 + p1;
            ls1 += p2 + p3;
            float* pr0 = psf + (wr0 + r) * APAD + nt * 8 + 2 * j;
            float* pr1 = psf + (wr0 + r + 8) * APAD + nt * 8 + 2 * j;
            *(float2*)pr0 = make_float2(p0, p1);
            *(float2*)pr1 = make_float2(p2, p3);
        }
        ls0 += __shfl_xor_sync(0xffffffffu, ls0, 1);
        ls0 += __shfl_xor_sync(0xffffffffu, ls0, 2);
        ls1 += __shfl_xor_sync(0xffffffffu, ls1, 1);
        ls1 += __shfl_xor_sync(0xffffffffu, ls1, 2);
        l0 = l0 * corr0 + ls0;
        l1 = l1 * corr1 + ls1;

#pragma unroll
        for (int nt = 0; nt < 8; nt++) {
            o[nt][0] *= corr0; o[nt][1] *= corr0;
            o[nt][2] *= corr1; o[nt][3] *= corr1;
        }

        // wait for v_i (q_{i+1} may still be in flight on non-final steps)
        if (s0 < t0) { CP_WAIT1(); } else { CP_WAIT0(); }
        __syncthreads();   // barB: v_i visible to all warps; ps stores drained

        // ---- GEMM2: O += P . V  (A = P from ps, B = V^T tile) ----
#pragma unroll
        for (int kk = 0; kk < 8; kk++) {
            uint32_t a0, a1, a2, a3;
            ldsm_x4(a0, a1, a2, a3, ps_u + (wr0 * APAD + aoff + kk * 8) * 4);
#pragma unroll
            for (int nt2 = 0; nt2 < 4; nt2++) {
                uint32_t b0, b1, b2, b3;
                ldsm_x4(b0, b1, b2, b3,
                        vs_u + (boff + nt2 * 16 * APAD + kk * 8) * 4);
                mma_tf32(o[nt2*2][0], o[nt2*2][1], o[nt2*2][2], o[nt2*2][3],
                         a0, a1, a2, a3, b0, b1);
                mma_tf32(o[nt2*2+1][0], o[nt2*2+1][1], o[nt2*2+1][2], o[nt2*2+1][3],
                         a0, a1, a2, a3, b2, b3);
            }
        }
    }

    // epilogue
    const float inv0 = 1.f / l0;
    const float inv1 = 1.f / l1;
    float* op = out + (bbase + t0 + wr0) * HD;
#pragma unroll
    for (int nt = 0; nt < 8; nt++) {
        const int col = nt * 8 + 2 * j;
        *(float2*)&op[r * HD + col] =
            make_float2(o[nt][0] * inv0, o[nt][1] * inv0);
        *(float2*)&op[(r + 8) * HD + col] =
            make_float2(o[nt][2] * inv1, o[nt][3] * inv1);
    }
}

extern "C" void kernel_launch(void* const* d_in, const int* in_sizes, int n_in,
                              void* d_out, int out_size)
{
    const float* x  = (const float*)d_in[0];
    const float* Wq = (const float*)d_in[1];
    const float* Wk = (const float*)d_in[2];
    const float* Wv = (const float*)d_in[3];
    float* out = (float*)d_out;

    cudaFuncSetAttribute(attn_mma_kernel, cudaFuncAttributeMaxDynamicSharedMemorySize,
                         ATTN_SMEM_BYTES);

    proj_mma_kernel<<<BT / 128, 256>>>(x, Wq, Wk, Wv);
    attn_mma_kernel<<<256, 128, ATTN_SMEM_BYTES>>>(out);
}